// round 4
// baseline (speedup 1.0000x reference)
#include <cuda_runtime.h>
#include <cstdint>
#include <cstddef>

// Problem dims (fixed by reference)
#define Bb 256
#define Tt 512
#define Dd 64
#define Ll 32
#define Hh 128
#define G4 512   // 4*H

// ---------------- scratch (device globals; no allocation allowed) ----------
__device__ float g_pre[(size_t)Bb * Tt * G4];   // 268 MB: pre-activations
__device__ float g_stat[Bb * G4];               // static part: x_static@Wzh^T + b

// ---------------- math helpers ---------------------------------------------
__device__ __forceinline__ float sigf(float x) {
    return __fdividef(1.0f, 1.0f + __expf(-x));
}
__device__ __forceinline__ float tanhf_fast(float x) {
    x = fminf(20.0f, fmaxf(-20.0f, x));
    float e = __expf(-2.0f * x);
    return __fdividef(1.0f - e, 1.0f + e);
}

// packed fp32x2 helpers (sm_103a)
__device__ __forceinline__ unsigned long long pk2(float lo, float hi) {
    unsigned long long r;
    asm("mov.b64 %0, {%1, %2};" : "=l"(r) : "f"(lo), "f"(hi));
    return r;
}
__device__ __forceinline__ float2 upk2(unsigned long long v) {
    float2 f;
    asm("mov.b64 {%0, %1}, %2;" : "=f"(f.x), "=f"(f.y) : "l"(v));
    return f;
}
__device__ __forceinline__ void fma2(unsigned long long& d,
                                     unsigned long long a, unsigned long long b) {
    asm("fma.rn.f32x2 %0, %1, %2, %0;" : "+l"(d) : "l"(a), "l"(b));
}
__device__ __forceinline__ unsigned long long add2(unsigned long long a,
                                                   unsigned long long b) {
    unsigned long long r;
    asm("add.rn.f32x2 %0, %1, %2;" : "=l"(r) : "l"(a), "l"(b));
    return r;
}

// ---------------- mbarrier / st.async helpers -------------------------------
__device__ __forceinline__ void mbar_init(uint32_t addr, uint32_t cnt) {
    asm volatile("mbarrier.init.shared.b64 [%0], %1;" :: "r"(addr), "r"(cnt) : "memory");
}
__device__ __forceinline__ void mbar_arrive_expect_tx(uint32_t addr, uint32_t tx) {
    asm volatile("mbarrier.arrive.expect_tx.shared.b64 _, [%0], %1;"
                 :: "r"(addr), "r"(tx) : "memory");
}
__device__ __forceinline__ void mbar_wait(uint32_t addr, uint32_t parity) {
    uint32_t done;
    asm volatile(
        "{\n\t.reg .pred p;\n\t"
        "mbarrier.try_wait.parity.acquire.cluster.shared::cta.b64 p, [%1], %2;\n\t"
        "selp.b32 %0, 1, 0, p;\n\t}"
        : "=r"(done) : "r"(addr), "r"(parity) : "memory");
    while (!done) {
        asm volatile(
            "{\n\t.reg .pred p;\n\t"
            "mbarrier.try_wait.parity.acquire.cluster.shared::cta.b64 p, [%1], %2, 0x989680;\n\t"
            "selp.b32 %0, 1, 0, p;\n\t}"
            : "=r"(done) : "r"(addr), "r"(parity) : "memory");
    }
}
__device__ __forceinline__ void st_async64(uint32_t dst, unsigned long long v,
                                           uint32_t mbar) {
    asm volatile(
        "st.async.shared::cluster.mbarrier::complete_tx::bytes.u64 [%0], %1, [%2];"
        :: "r"(dst), "l"(v), "r"(mbar) : "memory");
}

// ============================================================================
// Kernel 1: g_stat[b][g] = sum_l x_static[b][l] * W_zh[g][l] + b[g]
// ============================================================================
__global__ __launch_bounds__(512) void static_kernel(
    const float* __restrict__ xs, const float* __restrict__ Wzh,
    const float* __restrict__ bvec)
{
    __shared__ float xrow[Ll];
    int bb = blockIdx.x;
    int g  = threadIdx.x;
    if (g < Ll) xrow[g] = xs[bb * Ll + g];
    __syncthreads();
    float acc = bvec[g];
    const float* w = Wzh + g * Ll;
#pragma unroll
    for (int l = 0; l < Ll; l++) acc += xrow[l] * w[l];
    g_stat[bb * G4 + g] = acc;
}

// ============================================================================
// Kernel 2: g_pre[m][n] = sum_k x_dyn[m][k]*W_ih[n][k] + g_stat[b][n]
//   M = 131072, N = 512, K = 64.  Tiles 64(M) x 128(N), full K.
//   W tile stored TRANSPOSED [k][n] so n-pairs load as LDS.64 -> fma.rn.f32x2.
// ============================================================================
#define PRE_MT 64
#define PRE_NT 128
#define PRE_PADX 65
#define PRE_PADN 128
#define PRE_SMEM ((PRE_MT * PRE_PADX + Dd * PRE_PADN) * 4)   // 49408 bytes

__global__ __launch_bounds__(256) void pre_kernel(
    const float* __restrict__ xd, const float* __restrict__ Wih)
{
    extern __shared__ float sm[];
    float* xsm  = sm;                        // [64][65]  (m-major)
    float* wsmT = sm + PRE_MT * PRE_PADX;    // [64 k][128 n]

    int t  = threadIdx.x;
    int m0 = blockIdx.x * PRE_MT;
    int n0 = blockIdx.y * PRE_NT;

    // x tile fill (coalesced float4 loads)
    {
        const float4* xg = (const float4*)(xd + (size_t)m0 * Dd);
        for (int i = t; i < PRE_MT * (Dd / 4); i += 256) {
            int row = i >> 4, dq = i & 15;
            float4 v = xg[row * 16 + dq];
            float* dst = xsm + row * PRE_PADX + dq * 4;
            dst[0] = v.x; dst[1] = v.y; dst[2] = v.z; dst[3] = v.w;
        }
    }
    // W tile fill, transposed into [k][n]
    {
        for (int i = t; i < PRE_NT * (Dd / 4); i += 256) {
            int n  = i & 127;
            int kq = i >> 7;
            float4 v = *(const float4*)(Wih + (size_t)(n0 + n) * Dd + kq * 4);
            wsmT[(kq * 4 + 0) * PRE_PADN + n] = v.x;
            wsmT[(kq * 4 + 1) * PRE_PADN + n] = v.y;
            wsmT[(kq * 4 + 2) * PRE_PADN + n] = v.z;
            wsmT[(kq * 4 + 3) * PRE_PADN + n] = v.w;
        }
    }
    __syncthreads();

    int tn = t & 15;   // n pair base: n = tn*2 + 32*jj (+ {0,1})
    int tm = t >> 4;   // m = tm + 16*i

    unsigned long long acc[4][4];
#pragma unroll
    for (int i = 0; i < 4; i++)
#pragma unroll
        for (int jj = 0; jj < 4; jj++) acc[i][jj] = 0ull;

#pragma unroll 8
    for (int k = 0; k < Dd; k++) {
        unsigned long long ap[4], bp[4];
#pragma unroll
        for (int i = 0; i < 4; i++) {
            float a = xsm[(tm + 16 * i) * PRE_PADX + k];
            ap[i] = pk2(a, a);
        }
#pragma unroll
        for (int jj = 0; jj < 4; jj++)
            bp[jj] = *(const unsigned long long*)(wsmT + k * PRE_PADN + tn * 2 + 32 * jj);
#pragma unroll
        for (int i = 0; i < 4; i++)
#pragma unroll
            for (int jj = 0; jj < 4; jj++) fma2(acc[i][jj], ap[i], bp[jj]);
    }

    // Epilogue: add static part (paired), store as 8B writes
    int bb = m0 >> 9;   // T = 512
    const float* srow = g_stat + bb * G4 + n0;
    unsigned long long sv[4];
#pragma unroll
    for (int jj = 0; jj < 4; jj++)
        sv[jj] = *(const unsigned long long*)(srow + tn * 2 + 32 * jj);
#pragma unroll
    for (int i = 0; i < 4; i++) {
        float* orow = g_pre + (size_t)(m0 + tm + 16 * i) * G4 + n0;
#pragma unroll
        for (int jj = 0; jj < 4; jj++)
            *(unsigned long long*)(orow + tn * 2 + 32 * jj) = add2(acc[i][jj], sv[jj]);
    }
}

// ============================================================================
// Kernel 3: persistent LSTM scan.
//   2-CTA clusters, K-split of W_hh.
//   - W half: low 32 d in REGISTERS (32 regs), high 32 d in SMEM
//   - matvec on fma.rn.f32x2 (2 MAC/lane/issue)
//   - partial exchange via st.async -> peer mbarrier (complete_tx::bytes),
//     double-buffered; NO per-step cluster barrier (and no L1D flush)
// ============================================================================
#define NROW 4
// float offsets within dynamic smem
#define OFF_W    0                      // 8 chunks * 512 j * 4 = 16384 floats
#define OFF_H    16384                  // h[4][128]
#define OFF_RECV (OFF_H + 512)          // recv[2 buf][512 j][4 r]
#define OFF_G    (OFF_RECV + 4096)      // g[4][512]
#define OFF_RED  (OFF_G + 2048)         // red[16]
#define OFF_MBAR (OFF_RED + 16)         // 2 mbarriers (4 floats), 8B aligned
#define SCAN_SMEM ((OFF_MBAR + 4) * 4)  // 92240 bytes

__global__ void __cluster_dims__(2, 1, 1) __launch_bounds__(512, 1)
scan_kernel(const float* __restrict__ Whh, const float* __restrict__ Wout,
            const float* __restrict__ bout, float* __restrict__ out)
{
    extern __shared__ float sm[];
    int tid = threadIdx.x;
    uint32_t rank;
    asm("mov.u32 %0, %%cluster_ctarank;" : "=r"(rank));
    int cid = blockIdx.x >> 1;
    int b0  = cid * NROW;
    int j   = tid;                 // gate-column index 0..511
    int hoff = (int)rank * 64;     // this CTA's K half

    // ---- W low quarter (local d 0..31) into registers as f32x2 pairs
    unsigned long long wreg[16];
    {
        const float* ws = Whh + j * 128 + hoff;   // 16B-aligned
#pragma unroll
        for (int c = 0; c < 8; c++) {
            ulonglong2 v = *(const ulonglong2*)(ws + c * 4);
            wreg[2 * c]     = v.x;
            wreg[2 * c + 1] = v.y;
        }
    }
    // ---- W high quarter (local d 32..63) into smem: Wv[c][j][q]
    for (int idx = tid; idx < 512 * 32; idx += 512) {
        int jj = idx >> 5, dq = idx & 31;
        sm[OFF_W + (dq >> 2) * 2048 + jj * 4 + (dq & 3)] =
            Whh[jj * 128 + hoff + 32 + dq];
    }
    // zero h state
    sm[OFF_H + tid] = 0.0f;

    // smem 32-bit addresses
    uint32_t my32;
    asm("{ .reg .u64 t; cvta.to.shared.u64 t, %1; cvt.u32.u64 %0, t; }"
        : "=r"(my32) : "l"(sm));
    uint32_t peer32;
    uint32_t peer_rank = rank ^ 1u;
    asm("mapa.shared::cluster.u32 %0, %1, %2;"
        : "=r"(peer32) : "r"(my32), "r"(peer_rank));

    uint32_t my_mbar   = my32   + OFF_MBAR * 4;
    uint32_t peer_mbar = peer32 + OFF_MBAR * 4;
    if (tid == 0) {
        mbar_init(my_mbar, 1);
        mbar_init(my_mbar + 8, 1);
    }
    __syncthreads();
    // all init (W smem, h, mbars) visible cluster-wide before any st.async
    asm volatile("barrier.cluster.arrive.aligned;" ::: "memory");
    asm volatile("barrier.cluster.wait.aligned;" ::: "memory");

    int r2 = tid >> 7;        // row 0..3 (update role)
    int k  = tid & 127;       // hidden index (update role)

    float cst = 0.0f;         // cell state
    float wo  = Wout[k];
    float bo  = bout[0];

    const float* pre0 = g_pre + ((size_t)(b0 + 0) * Tt) * G4 + j;
    const float* pre1 = g_pre + ((size_t)(b0 + 1) * Tt) * G4 + j;
    const float* pre2 = g_pre + ((size_t)(b0 + 2) * Tt) * G4 + j;
    const float* pre3 = g_pre + ((size_t)(b0 + 3) * Tt) * G4 + j;

    // peer recv slot for this thread: recv[buf][j][0..3]
    uint32_t peer_recv = peer32 + OFF_RECV * 4 + (uint32_t)j * 16u;
    const float* hsh = sm + OFF_H;

    int buf = 0;
    for (int t = 0; t < Tt; t++) {
        // announce expected bytes for this step's recv buffer (1 arrival + tx)
        if (tid == 0) mbar_arrive_expect_tx(my_mbar + buf * 8, 512u * 16u);

        // issue pre loads early (consumed after the wait)
        float p0 = pre0[(size_t)t * G4];
        float p1 = pre1[(size_t)t * G4];
        float p2 = pre2[(size_t)t * G4];
        float p3 = pre3[(size_t)t * G4];

        // half matvec on f32x2: acc_r = sum_d W[j][hoff+d] * h[r][hoff+d]
        unsigned long long a0 = 0ull, a1 = 0ull, a2 = 0ull, a3 = 0ull;
        const float* hp = hsh + hoff;
#pragma unroll
        for (int c = 0; c < 8; c++) {   // local d 0..31 (register weights)
            ulonglong2 h0 = *(const ulonglong2*)(hp + 0 * 128 + c * 4);
            ulonglong2 h1 = *(const ulonglong2*)(hp + 1 * 128 + c * 4);
            ulonglong2 h2 = *(const ulonglong2*)(hp + 2 * 128 + c * 4);
            ulonglong2 h3 = *(const ulonglong2*)(hp + 3 * 128 + c * 4);
            fma2(a0, wreg[2 * c], h0.x);  fma2(a0, wreg[2 * c + 1], h0.y);
            fma2(a1, wreg[2 * c], h1.x);  fma2(a1, wreg[2 * c + 1], h1.y);
            fma2(a2, wreg[2 * c], h2.x);  fma2(a2, wreg[2 * c + 1], h2.y);
            fma2(a3, wreg[2 * c], h3.x);  fma2(a3, wreg[2 * c + 1], h3.y);
        }
#pragma unroll
        for (int c = 0; c < 8; c++) {   // local d 32..63 (smem weights)
            ulonglong2 w  = *(const ulonglong2*)(sm + OFF_W + c * 2048 + j * 4);
            ulonglong2 h0 = *(const ulonglong2*)(hp + 0 * 128 + 32 + c * 4);
            ulonglong2 h1 = *(const ulonglong2*)(hp + 1 * 128 + 32 + c * 4);
            ulonglong2 h2 = *(const ulonglong2*)(hp + 2 * 128 + 32 + c * 4);
            ulonglong2 h3 = *(const ulonglong2*)(hp + 3 * 128 + 32 + c * 4);
            fma2(a0, w.x, h0.x);  fma2(a0, w.y, h0.y);
            fma2(a1, w.x, h1.x);  fma2(a1, w.y, h1.y);
            fma2(a2, w.x, h2.x);  fma2(a2, w.y, h2.y);
            fma2(a3, w.x, h3.x);  fma2(a3, w.y, h3.y);
        }
        float2 f0 = upk2(a0), f1 = upk2(a1), f2 = upk2(a2), f3 = upk2(a3);
        float acc0 = f0.x + f0.y;
        float acc1 = f1.x + f1.y;
        float acc2 = f2.x + f2.y;
        float acc3 = f3.x + f3.y;

        // send partials to peer recv[buf][j][0..3] with tx-completion on its mbar
        {
            uint32_t dst = peer_recv + (uint32_t)buf * 8192u;
            st_async64(dst,     pk2(acc0, acc1), peer_mbar + buf * 8);
            st_async64(dst + 8, pk2(acc2, acc3), peer_mbar + buf * 8);
        }

        // wait for peer's 8192 bytes (phase parity flips once per use)
        mbar_wait(my_mbar + buf * 8, (uint32_t)((t >> 1) & 1));

        // full gate pre-activation (own-half + peer-half; addition commutes ->
        // bitwise-identical replicas), staged for the (r,k) transpose
        {
            float4 rv = *(const float4*)(sm + OFF_RECV + (buf * 512 + j) * 4);
            sm[OFF_G + 0 * 512 + j] = p0 + (acc0 + rv.x);
            sm[OFF_G + 1 * 512 + j] = p1 + (acc1 + rv.y);
            sm[OFF_G + 2 * 512 + j] = p2 + (acc2 + rv.z);
            sm[OFF_G + 3 * 512 + j] = p3 + (acc3 + rv.w);
        }
        __syncthreads();

        // state update (replicated on both CTAs)
        float gi = sm[OFF_G + r2 * 512 + k];
        float gf = sm[OFF_G + r2 * 512 + 128 + k];
        float gc = sm[OFF_G + r2 * 512 + 256 + k];
        float go = sm[OFF_G + r2 * 512 + 384 + k];
        cst = sigf(gf) * cst + sigf(gi) * tanhf_fast(gc);
        float hval = sigf(go) * tanhf_fast(cst);
        sm[OFF_H + r2 * 128 + k] = hval;

        // fused O=1 head (rank 0 reduces + writes)
        if (rank == 0) {
            float v = hval * wo;
            v += __shfl_down_sync(0xffffffffu, v, 16);
            v += __shfl_down_sync(0xffffffffu, v, 8);
            v += __shfl_down_sync(0xffffffffu, v, 4);
            v += __shfl_down_sync(0xffffffffu, v, 2);
            v += __shfl_down_sync(0xffffffffu, v, 1);
            if ((tid & 31) == 0) sm[OFF_RED + (tid >> 5)] = v;
        }
        __syncthreads();   // guards h_sh for next matvec + red readiness

        if (rank == 0 && tid < NROW) {
            const float* rd = sm + OFF_RED + tid * 4;
            out[(size_t)(b0 + tid) * Tt + t] = rd[0] + rd[1] + rd[2] + rd[3] + bo;
        }
        buf ^= 1;
    }

    // keep cluster alive until both CTAs stop issuing remote traffic
    asm volatile("barrier.cluster.arrive.aligned;" ::: "memory");
    asm volatile("barrier.cluster.wait.aligned;" ::: "memory");
}

// ============================================================================
// launch
// ============================================================================
extern "C" void kernel_launch(void* const* d_in, const int* in_sizes, int n_in,
                              void* d_out, int out_size)
{
    const float* x_dyn = (const float*)d_in[0];
    const float* x_sta = (const float*)d_in[1];
    const float* W_ih  = (const float*)d_in[2];
    const float* W_hh  = (const float*)d_in[3];
    const float* W_zh  = (const float*)d_in[4];
    const float* bvec  = (const float*)d_in[5];
    const float* W_out = (const float*)d_in[6];
    const float* b_out = (const float*)d_in[7];
    float* out = (float*)d_out;

    (void)in_sizes; (void)n_in; (void)out_size;

    cudaFuncSetAttribute(pre_kernel,
                         cudaFuncAttributeMaxDynamicSharedMemorySize, PRE_SMEM);
    cudaFuncSetAttribute(scan_kernel,
                         cudaFuncAttributeMaxDynamicSharedMemorySize, SCAN_SMEM);

    static_kernel<<<Bb, G4>>>(x_sta, W_zh, bvec);

    dim3 pre_grid((Bb * Tt) / PRE_MT, G4 / PRE_NT);   // 2048 x 4
    pre_kernel<<<pre_grid, 256, PRE_SMEM>>>(x_dyn, W_ih);

    scan_kernel<<<128, 512, SCAN_SMEM>>>(W_hh, W_out, b_out, out);
}

// round 5
// speedup vs baseline: 1.1656x; 1.1656x over previous
#include <cuda_runtime.h>
#include <cstdint>
#include <cstddef>

// Problem dims (fixed by reference)
#define Bb 256
#define Tt 512
#define Dd 64
#define Ll 32
#define Hh 128
#define G4 512   // 4*H

// ---------------- scratch (device globals; no allocation allowed) ----------
__device__ float g_pre[(size_t)Bb * Tt * G4];   // 268 MB: pre-activations

// ---------------- math helpers ---------------------------------------------
__device__ __forceinline__ float sigf(float x) {
    return __fdividef(1.0f, 1.0f + __expf(-x));
}
__device__ __forceinline__ float tanhf_fast(float x) {
    x = fminf(20.0f, fmaxf(-20.0f, x));
    float e = __expf(-2.0f * x);
    return __fdividef(1.0f - e, 1.0f + e);
}

// ============================================================================
// Kernel 1: pre-GEMM with fused static part.
//   g_pre[m][n] = sum_k x_dyn[m][k]*W_ih[n][k] + (x_static[b] @ W_zh^T + b)[n]
//   M = 131072, N = 512, K = 64.  Tiles 64(M) x 128(N), full K.  Scalar FFMA
//   (R1-proven body).  The static 128-vector for this (block,b) is computed
//   once into smem by the first 128 threads (32 MACs each — negligible).
// ============================================================================
#define PRE_MT 64
#define PRE_NT 128
#define PRE_PAD 65
#define PRE_SMEM (((PRE_MT + PRE_NT) * PRE_PAD + PRE_NT) * 4)   // 50432 bytes

__global__ __launch_bounds__(256) void pre_kernel(
    const float* __restrict__ xd, const float* __restrict__ Wih,
    const float* __restrict__ xs, const float* __restrict__ Wzh,
    const float* __restrict__ bvec)
{
    extern __shared__ float sm[];
    float* xsm   = sm;                                  // [64][65]
    float* wsm   = sm + PRE_MT * PRE_PAD;               // [128][65]
    float* svrow = sm + (PRE_MT + PRE_NT) * PRE_PAD;    // [128]

    int t  = threadIdx.x;
    int m0 = blockIdx.x * PRE_MT;
    int n0 = blockIdx.y * PRE_NT;
    int bb = m0 >> 9;   // T = 512

    // x tile fill (coalesced float4 loads)
    {
        const float4* xg = (const float4*)(xd + (size_t)m0 * Dd);
        for (int i = t; i < PRE_MT * (Dd / 4); i += 256) {
            int row = i >> 4, dq = i & 15;
            float4 v = xg[row * 16 + dq];
            float* dst = xsm + row * PRE_PAD + dq * 4;
            dst[0] = v.x; dst[1] = v.y; dst[2] = v.z; dst[3] = v.w;
        }
    }
    // W tile fill
    {
        const float4* wg = (const float4*)(Wih + (size_t)n0 * Dd);
        for (int i = t; i < PRE_NT * (Dd / 4); i += 256) {
            int row = i >> 4, dq = i & 15;
            float4 v = wg[row * 16 + dq];
            float* dst = wsm + row * PRE_PAD + dq * 4;
            dst[0] = v.x; dst[1] = v.y; dst[2] = v.z; dst[3] = v.w;
        }
    }
    // fused static: svrow[n] = b[n0+n] + sum_l xs[bb][l] * Wzh[n0+n][l]
    if (t < PRE_NT) {
        int gn = n0 + t;
        float acc = bvec[gn];
        const float* w = Wzh + gn * Ll;
        const float* xr = xs + bb * Ll;
#pragma unroll
        for (int l = 0; l < Ll; l++) acc += xr[l] * w[l];
        svrow[t] = acc;
    }
    __syncthreads();

    int tn = t & 15;       // n fragment: n = tn + 16*jj
    int tm = t >> 4;       // m fragment: m = tm + 16*i

    float acc[4][8];
#pragma unroll
    for (int i = 0; i < 4; i++)
#pragma unroll
        for (int jj = 0; jj < 8; jj++) acc[i][jj] = 0.0f;

#pragma unroll 8
    for (int k = 0; k < Dd; k++) {
        float a[4], b[8];
#pragma unroll
        for (int i = 0; i < 4; i++)  a[i]  = xsm[(tm + 16 * i) * PRE_PAD + k];
#pragma unroll
        for (int jj = 0; jj < 8; jj++) b[jj] = wsm[(tn + 16 * jj) * PRE_PAD + k];
#pragma unroll
        for (int i = 0; i < 4; i++)
#pragma unroll
            for (int jj = 0; jj < 8; jj++) acc[i][jj] += a[i] * b[jj];
    }

    // Epilogue: add static part, write pre
    float sv[8];
#pragma unroll
    for (int jj = 0; jj < 8; jj++) sv[jj] = svrow[tn + 16 * jj];
#pragma unroll
    for (int i = 0; i < 4; i++) {
        float* orow = g_pre + (size_t)(m0 + tm + 16 * i) * G4 + n0;
#pragma unroll
        for (int jj = 0; jj < 8; jj++) orow[tn + 16 * jj] = acc[i][jj] + sv[jj];
    }
}

// ============================================================================
// Kernel 2: persistent LSTM scan — INDEPENDENT CTAs (no cluster!).
//   128 CTAs x 2 batch rows each.  Full W_hh per CTA:
//     d 0..95  -> smem  (192 KB, float4-chunked, conflict-free)
//     d 96..127-> 32 scalar registers per thread
//   Per step: full matvec for 2 rows (scalar FFMA, 256 MAC/thread) ->
//   stage gates -> state update -> fused O=1 head.  Only 2 bar.sync/step;
//   zero cross-CTA traffic.
// ============================================================================
#define NCH 24   // smem W chunks of 4 d-values (d 0..95)
// float offsets within dynamic smem
#define OFF_W    0                        // 24 * 512 * 4 = 49152 floats (192KB)
#define OFF_H    (NCH * 2048)             // h[2][128]
#define OFF_G    (OFF_H + 256)            // g[2][512]
#define OFF_RED  (OFF_G + 1024)           // red[8]
#define SCAN_SMEM ((OFF_RED + 8) * 4)     // 201760 bytes

__global__ void __launch_bounds__(512, 1)
scan_kernel(const float* __restrict__ Whh, const float* __restrict__ Wout,
            const float* __restrict__ bout, float* __restrict__ out)
{
    extern __shared__ float sm[];
    int tid = threadIdx.x;
    int b0  = blockIdx.x * 2;
    int j   = tid;                 // gate-column index 0..511

    // ---- W d 0..95 into smem: Wv[c][j][q] = W_hh[j][4c+q]
#pragma unroll 4
    for (int c = 0; c < NCH; c++) {
        float4 v = *(const float4*)(Whh + (size_t)j * 128 + c * 4);
        float* dst = sm + OFF_W + c * 2048 + j * 4;
        dst[0] = v.x; dst[1] = v.y; dst[2] = v.z; dst[3] = v.w;
    }
    // ---- W d 96..127 into 32 scalar registers
    float wr[32];
    {
        const float* ws = Whh + (size_t)j * 128 + 96;
#pragma unroll
        for (int c = 0; c < 8; c++) {
            float4 v = *(const float4*)(ws + c * 4);
            wr[4 * c + 0] = v.x; wr[4 * c + 1] = v.y;
            wr[4 * c + 2] = v.z; wr[4 * c + 3] = v.w;
        }
    }
    // zero h state
    if (tid < 256) sm[OFF_H + tid] = 0.0f;
    __syncthreads();

    int r2 = tid >> 7;        // row 0..1 (update role, tid < 256)
    int k  = tid & 127;       // hidden index (update role)

    float cst = 0.0f;         // cell state (threads 0..255)
    float wo  = (tid < 256) ? Wout[k] : 0.0f;
    float bo  = bout[0];

    const float* pre0 = g_pre + ((size_t)(b0 + 0) * Tt) * G4 + j;
    const float* pre1 = g_pre + ((size_t)(b0 + 1) * Tt) * G4 + j;
    const float* hsh  = sm + OFF_H;

    for (int t = 0; t < Tt; t++) {
        // prefetch pre values (consumed after matvec)
        float p0 = pre0[(size_t)t * G4];
        float p1 = pre1[(size_t)t * G4];

        // full matvec, scalar FFMA: acc_r = sum_d W[j][d] * h[r][d]
        float acc0 = 0.0f, acc1 = 0.0f;
#pragma unroll
        for (int c = 0; c < NCH; c++) {          // d 0..95 (smem weights)
            float4 w  = *(const float4*)(sm + OFF_W + c * 2048 + j * 4);
            float4 h0 = *(const float4*)(hsh + 0 * 128 + c * 4);
            float4 h1 = *(const float4*)(hsh + 1 * 128 + c * 4);
            acc0 += w.x * h0.x + w.y * h0.y + w.z * h0.z + w.w * h0.w;
            acc1 += w.x * h1.x + w.y * h1.y + w.z * h1.z + w.w * h1.w;
        }
#pragma unroll
        for (int c = 0; c < 8; c++) {            // d 96..127 (register weights)
            float4 h0 = *(const float4*)(hsh + 0 * 128 + 96 + c * 4);
            float4 h1 = *(const float4*)(hsh + 1 * 128 + 96 + c * 4);
            acc0 += wr[4*c] * h0.x + wr[4*c+1] * h0.y + wr[4*c+2] * h0.z + wr[4*c+3] * h0.w;
            acc1 += wr[4*c] * h1.x + wr[4*c+1] * h1.y + wr[4*c+2] * h1.z + wr[4*c+3] * h1.w;
        }

        // stage full gate pre-activations
        sm[OFF_G + 0 * 512 + j] = p0 + acc0;
        sm[OFF_G + 1 * 512 + j] = p1 + acc1;
        __syncthreads();

        // state update (threads 0..255: 2 rows x 128 hidden)
        if (tid < 256) {
            float gi = sm[OFF_G + r2 * 512 + k];
            float gf = sm[OFF_G + r2 * 512 + 128 + k];
            float gc = sm[OFF_G + r2 * 512 + 256 + k];
            float go = sm[OFF_G + r2 * 512 + 384 + k];
            cst = sigf(gf) * cst + sigf(gi) * tanhf_fast(gc);
            float hval = sigf(go) * tanhf_fast(cst);
            sm[OFF_H + r2 * 128 + k] = hval;

            // fused O=1 head: warp-reduce hval*wo (warps 0..7)
            float v = hval * wo;
            v += __shfl_down_sync(0xffffffffu, v, 16);
            v += __shfl_down_sync(0xffffffffu, v, 8);
            v += __shfl_down_sync(0xffffffffu, v, 4);
            v += __shfl_down_sync(0xffffffffu, v, 2);
            v += __shfl_down_sync(0xffffffffu, v, 1);
            if ((tid & 31) == 0) sm[OFF_RED + (tid >> 5)] = v;
        }
        __syncthreads();   // guards h for next matvec + red readiness

        if (tid < 2) {
            const float* rd = sm + OFF_RED + tid * 4;
            out[(size_t)(b0 + tid) * Tt + t] = rd[0] + rd[1] + rd[2] + rd[3] + bo;
        }
    }
}

// ============================================================================
// launch
// ============================================================================
extern "C" void kernel_launch(void* const* d_in, const int* in_sizes, int n_in,
                              void* d_out, int out_size)
{
    const float* x_dyn = (const float*)d_in[0];
    const float* x_sta = (const float*)d_in[1];
    const float* W_ih  = (const float*)d_in[2];
    const float* W_hh  = (const float*)d_in[3];
    const float* W_zh  = (const float*)d_in[4];
    const float* bvec  = (const float*)d_in[5];
    const float* W_out = (const float*)d_in[6];
    const float* b_out = (const float*)d_in[7];
    float* out = (float*)d_out;

    (void)in_sizes; (void)n_in; (void)out_size;

    cudaFuncSetAttribute(pre_kernel,
                         cudaFuncAttributeMaxDynamicSharedMemorySize, PRE_SMEM);
    cudaFuncSetAttribute(scan_kernel,
                         cudaFuncAttributeMaxDynamicSharedMemorySize, SCAN_SMEM);

    dim3 pre_grid((Bb * Tt) / PRE_MT, G4 / PRE_NT);   // 2048 x 4
    pre_kernel<<<pre_grid, 256, PRE_SMEM>>>(x_dyn, W_ih, x_sta, W_zh, bvec);

    scan_kernel<<<128, 512, SCAN_SMEM>>>(W_hh, W_out, b_out, out);
}